// round 15
// baseline (speedup 1.0000x reference)
#include <cuda_runtime.h>
#include <cuda_bf16.h>
#include <cstdint>

// Problem constants
#define Bb    32
#define Ll    4096
#define Cc    128
#define OUTD  257          // 1 delta + 128 probs + 128 amt
#define CL    128          // stored steps per block -> 1024 blocks (residency!)
#define HALO  192          // 0.9^192 ~ 1.6e-9 -> below fp32 noise
#define MAXN  (CL + HALO)  // 320
#define TT    8            // rows per staged tile
#define NTILE (CL / TT)    // 16
#define NBUF  3            // staging ring depth (2 copies in flight)

#define MOM   0.9f
#define OMM   0.1f

__device__ __forceinline__ uint32_t smem_u32(const void* p) {
    uint32_t a;
    asm("{ .reg .u64 t; cvta.to.shared.u64 t, %1; cvt.u32.u64 %0, t; }"
        : "=r"(a) : "l"(p));
    return a;
}

__global__ __launch_bounds__(160, 7)
void mpe_kernel(const float* __restrict__ ts,
                const int*   __restrict__ labels,
                const float* __restrict__ amounts,
                float*       __restrict__ out)
{
    __shared__ uint2 s_la[MAXN];                           // .x=label, .y=bits(0.1*amount)
    __shared__ float s_dl[MAXN];                           // clipped deltas
    __shared__ __align__(16) float s_out[NBUF][TT * OUTD]; // staging ring

    const int chunk = blockIdx.x;
    const int b     = blockIdx.y;
    const int t0    = chunk * CL;
    const int s0    = (t0 - HALO) > 0 ? (t0 - HALO) : 0;
    const int N     = t0 + CL - s0;
    const int warm  = t0 - s0;      // 0 (chunk 0), 128 (chunk 1), 192 (chunks >= 2)
    const int tid   = threadIdx.x;

    const float* tsb = ts      + (size_t)b * Ll;
    const int*   lb  = labels  + (size_t)b * Ll;
    const float* ab  = amounts + (size_t)b * Ll;

    // L2 evict_last for output stores (keeps write-back traffic down; neutral-to-helpful)
    uint64_t pol;
    asm("createpolicy.fractional.L2::evict_last.b64 %0, 1.0;" : "=l"(pol));

    // ---- cooperative preload (amounts pre-scaled by 0.1) ----
    for (int i = tid; i < N; i += blockDim.x) {
        const int g = s0 + i;
        s_la[i] = make_uint2((unsigned)lb[g], __float_as_uint(OMM * ab[g]));
        float d = 0.0f;
        if (g > 0) d = fminf(tsb[g] - tsb[g - 1], 100.0f);
        s_dl[i] = d;
    }
    __syncthreads();

    // ---- per-thread state ----
    float p = 0.0f, a = 0.0f, dcar = 0.0f;
    const int c = tid;
    int i0 = 0;

    if (s0 == 0 && tid < Cc) {
        // Window starts at the true sequence start: EXACT carry-init with x0.
        // (x0's scan coefficient is 0.9^n, not 0.1*0.9^n — zero-init here
        //  breaks the amt clip boundary; R12's failure mode.)
        const uint2 la0 = s_la[0];
        const bool eq0 = ((int)la0.x == c);
        p = eq0 ? 1.0f : 0.0f;
        a = eq0 ? 10.0f * __uint_as_float(la0.y) : 0.0f;
        i0 = 1;                    // x0 consumed as the carry
    }
    // delta carry: dl[0] == 0 -> dcar = 0 exact in all cases

    if (tid < Cc) {
        // dense branchless warm-up; exact when s0==0, truncation <= 0.9^192 otherwise
        #pragma unroll 8
        for (int i = i0; i < warm; i++) {
            const uint2 v = s_la[i];
            const bool eq = ((int)v.x == c);
            p = MOM * p + (eq ? OMM : 0.0f);
            a = MOM * a + (eq ? __uint_as_float(v.y) : 0.0f);
        }
    } else if (tid == Cc) {
        #pragma unroll 8
        for (int i = 0; i < warm; i++)
            dcar = MOM * dcar + OMM * s_dl[i];
    }

    // ---- stored steps: dense scan into 3-deep staging ring, async drain ----
    const char* gbase = (const char*)(out + (size_t)(b * Ll + t0) * OUTD);
    for (int tile = 0; tile < NTILE; tile++) {
        float* ob = s_out[tile % NBUF];
        const int base = warm + tile * TT;

        if (tid < Cc) {
            const uint2* la = s_la + base;
            #pragma unroll
            for (int j = 0; j < TT; j++) {
                const uint2 v = la[j];
                const bool eq = ((int)v.x == c);
                p = MOM * p + (eq ? OMM : 0.0f);
                a = MOM * a + (eq ? __uint_as_float(v.y) : 0.0f);
                ob[j * OUTD + 1 + c]      = p;                              // probs (sum==1)
                ob[j * OUTD + 1 + Cc + c] = __fdividef(a, fmaxf(p, 1e-6f)); // amt
            }
        } else if (tid == Cc) {
            const float* dl = s_dl + base;
            #pragma unroll
            for (int j = 0; j < TT; j++) {
                dcar = MOM * dcar + OMM * dl[j];
                ob[j * OUTD] = dcar;
            }
        }
        __syncthreads();   // tile fully written

        if (tid == Cc + 1) {
            asm volatile("fence.proxy.async.shared::cta;" ::: "memory");
            const uint64_t gdst = (uint64_t)(gbase + (size_t)tile * TT * OUTD * 4);
            const uint32_t ssrc = smem_u32(ob);
            asm volatile("cp.async.bulk.global.shared::cta.bulk_group.L2::cache_hint "
                         "[%0], [%1], %2, %3;"
                         :: "l"(gdst), "r"(ssrc), "r"((uint32_t)(TT * OUTD * 4)), "l"(pol)
                         : "memory");
            asm volatile("cp.async.bulk.commit_group;" ::: "memory");
            // 2 copies in flight: guarantees copy (tile-2) done; buffer reused
            // at (tile+1) == (tile-2) mod 3 is free.
            asm volatile("cp.async.bulk.wait_group 2;" ::: "memory");
        }
        __syncthreads();   // reuse-safety broadcast
    }

    if (tid == Cc + 1)
        asm volatile("cp.async.bulk.wait_group 0;" ::: "memory");
    __syncthreads();       // keep smem alive until all copies land
}

extern "C" void kernel_launch(void* const* d_in, const int* in_sizes, int n_in,
                              void* d_out, int out_size)
{
    const float* ts      = (const float*)d_in[0];
    const int*   labels  = (const int*)  d_in[1];
    const float* amounts = (const float*)d_in[2];
    float* out = (float*)d_out;

    dim3 grid(Ll / CL, Bb);   // (32, 32) = 1024 blocks
    dim3 block(160);
    mpe_kernel<<<grid, block>>>(ts, labels, amounts, out);
}

// round 16
// speedup vs baseline: 1.1470x; 1.1470x over previous
#include <cuda_runtime.h>
#include <cuda_bf16.h>
#include <cstdint>

// Problem constants
#define Bb    32
#define Ll    4096
#define Cc    128
#define OUTD  257          // 1 delta + 128 probs + 128 amt
#define CL    128          // stored steps per block -> 1024 blocks (residency)
#define HALO  192          // 0.9^192 ~ 1.6e-9 -> below fp32 noise
#define MAXN  (CL + HALO)  // 320
#define TT    8            // rows per staged tile
#define NTILE (CL / TT)    // 16
#define NBUF  3            // staging ring depth (2 copies in flight)

#define MOM   0.9f
#define OMM   0.1f
#define LOG2_MOM (-0.15200309344504995f)   // log2(0.9)

__device__ __forceinline__ uint32_t smem_u32(const void* p) {
    uint32_t a;
    asm("{ .reg .u64 t; cvta.to.shared.u64 t, %1; cvt.u32.u64 %0, t; }"
        : "=r"(a) : "l"(p));
    return a;
}

__global__ __launch_bounds__(160, 7)
void mpe_kernel(const float* __restrict__ ts,
                const int*   __restrict__ labels,
                const float* __restrict__ amounts,
                float*       __restrict__ out)
{
    __shared__ uint2 s_la[MAXN];                           // .x=label, .y=bits(0.1*amount)
    __shared__ float s_dl[MAXN];                           // clipped deltas
    __shared__ __align__(16) float s_out[NBUF][TT * OUTD]; // staging ring
    __shared__ float s_pacc[Cc];                           // warm-state accumulators
    __shared__ float s_aacc[Cc];
    __shared__ float s_dacc;

    const int chunk = blockIdx.x;
    const int b     = blockIdx.y;
    const int t0    = chunk * CL;
    const int s0    = (t0 - HALO) > 0 ? (t0 - HALO) : 0;
    const int N     = t0 + CL - s0;
    const int warm  = t0 - s0;      // 0 (chunk 0), 128 (chunk 1), 192 (chunks >= 2)
    const int tid   = threadIdx.x;

    const float* tsb = ts      + (size_t)b * Ll;
    const int*   lb  = labels  + (size_t)b * Ll;
    const float* ab  = amounts + (size_t)b * Ll;

    // L2 evict_last for output stores (measured: reduces write-back traffic)
    uint64_t pol;
    asm("createpolicy.fractional.L2::evict_last.b64 %0, 1.0;" : "=l"(pol));

    // ---- zero accumulators + cooperative preload (amounts pre-scaled by 0.1) ----
    if (tid < Cc)       { s_pacc[tid] = 0.0f; s_aacc[tid] = 0.0f; }
    else if (tid == Cc) { s_dacc = 0.0f; }

    for (int i = tid; i < N; i += blockDim.x) {
        const int g = s0 + i;
        s_la[i] = make_uint2((unsigned)lb[g], __float_as_uint(OMM * ab[g]));
        float d = 0.0f;
        if (g > 0) d = fminf(tsb[g] - tsb[g - 1], 100.0f);
        s_dl[i] = d;
    }
    __syncthreads();

    // ---- warm-up via weighted scatter (replaces the O(C*warm) dense scan) ----
    // After warm steps: p = sum_i 0.1*0.9^(warm-1-i)*[lab_i==c],
    //                   a = sum_i 0.9^(warm-1-i)*(0.1*amt_i)   (+ x0 carry term)
    if (warm > 0) {
        float dsum = 0.0f;
        for (int i = tid; i < warm; i += blockDim.x) {
            const uint2 v = s_la[i];
            const float wa = exp2f((float)(warm - 1 - i) * LOG2_MOM); // 0.9^(warm-1-i)
            atomicAdd(&s_pacc[v.x], OMM * wa);
            atomicAdd(&s_aacc[v.x], wa * __uint_as_float(v.y));       // y is 0.1*amt
            dsum = fmaf(OMM * wa, s_dl[i], dsum);
        }
        // warp-reduce delta partials, one atomic per warp
        #pragma unroll
        for (int off = 16; off > 0; off >>= 1)
            dsum += __shfl_xor_sync(0xffffffffu, dsum, off);
        if ((tid & 31) == 0) atomicAdd(&s_dacc, dsum);

        if (s0 == 0 && tid == 0) {
            // exact-start carry term: x0 contributes with coefficient 0.9^warm
            // (NOT 0.1*0.9^warm — the R12 clip-boundary failure mode)
            const uint2 v0 = s_la[0];
            const float w0 = exp2f((float)warm * LOG2_MOM);
            atomicAdd(&s_pacc[v0.x], w0);
            atomicAdd(&s_aacc[v0.x], w0 * 10.0f * __uint_as_float(v0.y));
            // delta: dl[0] == 0 -> no carry term
        }
        __syncthreads();
    }

    // ---- load per-thread scan state ----
    float p = 0.0f, a = 0.0f, dcar = 0.0f;
    const int c = tid;
    if (tid < Cc) {
        if (warm == 0) {
            // chunk 0: exact carry-init (row 0 then emits exactly x0)
            const uint2 la0 = s_la[0];
            const bool eq0 = ((int)la0.x == c);
            p = eq0 ? 1.0f : 0.0f;
            a = eq0 ? 10.0f * __uint_as_float(la0.y) : 0.0f;
        } else {
            p = s_pacc[tid];
            a = s_aacc[tid];
        }
    } else if (tid == Cc) {
        dcar = s_dacc;              // == 0 for chunk 0
    }

    // ---- stored steps: dense scan into 3-deep staging ring, async drain ----
    const char* gbase = (const char*)(out + (size_t)(b * Ll + t0) * OUTD);
    for (int tile = 0; tile < NTILE; tile++) {
        float* ob = s_out[tile % NBUF];
        const int base = warm + tile * TT;

        if (tid < Cc) {
            const uint2* la = s_la + base;
            #pragma unroll
            for (int j = 0; j < TT; j++) {
                const uint2 v = la[j];
                const bool eq = ((int)v.x == c);
                p = MOM * p + (eq ? OMM : 0.0f);
                a = MOM * a + (eq ? __uint_as_float(v.y) : 0.0f);
                ob[j * OUTD + 1 + c]      = p;                              // probs (sum==1)
                ob[j * OUTD + 1 + Cc + c] = __fdividef(a, fmaxf(p, 1e-6f)); // amt
            }
        } else if (tid == Cc) {
            const float* dl = s_dl + base;
            #pragma unroll
            for (int j = 0; j < TT; j++) {
                dcar = MOM * dcar + OMM * dl[j];
                ob[j * OUTD] = dcar;
            }
        }
        __syncthreads();   // tile fully written

        if (tid == Cc + 1) {
            asm volatile("fence.proxy.async.shared::cta;" ::: "memory");
            const uint64_t gdst = (uint64_t)(gbase + (size_t)tile * TT * OUTD * 4);
            const uint32_t ssrc = smem_u32(ob);
            asm volatile("cp.async.bulk.global.shared::cta.bulk_group.L2::cache_hint "
                         "[%0], [%1], %2, %3;"
                         :: "l"(gdst), "r"(ssrc), "r"((uint32_t)(TT * OUTD * 4)), "l"(pol)
                         : "memory");
            asm volatile("cp.async.bulk.commit_group;" ::: "memory");
            // 2 copies in flight: buffer reused at (tile+1) is guaranteed drained
            asm volatile("cp.async.bulk.wait_group 2;" ::: "memory");
        }
        __syncthreads();   // reuse-safety broadcast
    }

    if (tid == Cc + 1)
        asm volatile("cp.async.bulk.wait_group 0;" ::: "memory");
    __syncthreads();       // keep smem alive until all copies land
}

extern "C" void kernel_launch(void* const* d_in, const int* in_sizes, int n_in,
                              void* d_out, int out_size)
{
    const float* ts      = (const float*)d_in[0];
    const int*   labels  = (const int*)  d_in[1];
    const float* amounts = (const float*)d_in[2];
    float* out = (float*)d_out;

    dim3 grid(Ll / CL, Bb);   // (32, 32) = 1024 blocks
    dim3 block(160);
    mpe_kernel<<<grid, block>>>(ts, labels, amounts, out);
}